// round 1
// baseline (speedup 1.0000x reference)
#include <cuda_runtime.h>

#define UNITS   64
#define TSTEPS  100
#define FDIM    3
#define TILE_B  64       // batch rows per CTA
#define NTHREADS 256     // 4 threads per batch row
#define QUNITS  16       // units per thread (quarter)

// shared memory layout (float offsets)
#define OFF_U   0                  // [64][64][4]  (k, unit, gate i/f/g/o) = 16384
#define OFF_W   16384              // [3][64][4]   = 768
#define OFF_BIA 17152              // [64][4]      = 256
#define OFF_H   17408              // [64][65]     = 4160
#define SMEM_FLOATS (17408 + 64*65)
#define SMEM_BYTES  (SMEM_FLOATS * 4)

// head-phase reuse offsets (inside the sU region, used after the step loop)
#define OFF_W1  0        // 64*64 = 4096
#define OFF_B1  4096     // 64
#define OFF_W2  4160     // 64*5 = 320
#define OFF_B2  4480     // 5 (padded 8)
#define OFF_H1  4488     // 64*65 = 4160

// ---------------- f32x2 packed-math helpers (Blackwell FFMA2 path) ----------
__device__ __forceinline__ unsigned long long pack2(float x) {
    unsigned long long r;
    asm("mov.b64 %0, {%1, %1};" : "=l"(r) : "f"(x));
    return r;
}
__device__ __forceinline__ void fma2(unsigned long long& d,
                                     unsigned long long a,
                                     unsigned long long b) {
    asm("fma.rn.f32x2 %0, %1, %2, %0;" : "+l"(d) : "l"(a), "l"(b));
}
__device__ __forceinline__ float2 unpack2(unsigned long long v) {
    float2 f;
    asm("mov.b64 {%0, %1}, %2;" : "=f"(f.x), "=f"(f.y) : "l"(v));
    return f;
}
__device__ __forceinline__ float ex2f_(float x) {
    float y; asm("ex2.approx.f32 %0, %1;" : "=f"(y) : "f"(x)); return y;
}
__device__ __forceinline__ float rcpf_(float x) {
    float y; asm("rcp.approx.f32 %0, %1;" : "=f"(y) : "f"(x)); return y;
}
// sigmoid(x) = 1/(1+2^(-x*log2e))
__device__ __forceinline__ float sigf_(float x) {
    return rcpf_(1.0f + ex2f_(-1.4426950408889634f * x));
}
// tanh(x) = 1 - 2/(2^(2x*log2e)+1)
__device__ __forceinline__ float tanhf_(float x) {
    return 1.0f - 2.0f * rcpf_(1.0f + ex2f_(2.8853900817779268f * x));
}

__global__ void __launch_bounds__(NTHREADS, 2)
lstm_kernel(const float* __restrict__ x,  const float* __restrict__ W,
            const float* __restrict__ U,  const float* __restrict__ b,
            const float* __restrict__ W1, const float* __restrict__ b1,
            const float* __restrict__ W2, const float* __restrict__ b2,
            float* __restrict__ out, int B)
{
    extern __shared__ float sm[];
    float* sU = sm + OFF_U;
    float* sW = sm + OFF_W;
    float* sB = sm + OFF_BIA;
    float* sH = sm + OFF_H;

    const int tid = threadIdx.x;
    const int bl  = tid & 63;          // local batch row
    const int q   = tid >> 6;          // quarter 0..3
    const int ub  = q * QUNITS;        // unit base for this thread
    const int bglob = blockIdx.x * TILE_B + bl;
    const bool valid_b = (bglob < B);
    const int bg = valid_b ? bglob : (B - 1);

    // ---- stage U with gate-interleaved layout: sU[(k*64+u)*4 + gate] ----
    for (int idx = tid; idx < 64 * 256; idx += NTHREADS) {
        int k = idx >> 8;
        int g = idx & 255;
        int gate = g >> 6, u = g & 63;
        sU[((k << 6) + u) * 4 + gate] = U[idx];
    }
    for (int idx = tid; idx < 3 * 256; idx += NTHREADS) {
        int f = idx >> 8;
        int g = idx & 255;
        int gate = g >> 6, u = g & 63;
        sW[((f << 6) + u) * 4 + gate] = W[idx];
    }
    for (int idx = tid; idx < 256; idx += NTHREADS) {
        int gate = idx >> 6, u = idx & 63;
        sB[u * 4 + gate] = b[idx];
    }
    for (int idx = tid; idx < 64 * 65; idx += NTHREADS) sH[idx] = 0.0f;

    float c[QUNITS];
    #pragma unroll
    for (int u = 0; u < QUNITS; u++) c[u] = 0.0f;

    __syncthreads();

    const float* xb = x + (size_t)bg * (TSTEPS * FDIM);
    float x0 = xb[0], x1 = xb[1], x2 = xb[2];

    float* shrow = sH + bl * 65;

    for (int t = 0; t < TSTEPS; t++) {
        const bool m = (x0 != 0.0f) || (x1 != 0.0f) || (x2 != 0.0f);
        const unsigned long long x0p = pack2(x0), x1p = pack2(x1), x2p = pack2(x2);

        // acc = bias + x @ W (for this thread's 16 units x 4 gates)
        unsigned long long aif[QUNITS], ago[QUNITS];
        #pragma unroll
        for (int u = 0; u < QUNITS; u++) {
            const int uu = ub + u;
            ulonglong2 bb = *(const ulonglong2*)(sB + uu * 4);
            unsigned long long t0 = bb.x, t1 = bb.y;
            ulonglong2 w0 = *(const ulonglong2*)(sW + uu * 4);
            fma2(t0, x0p, w0.x);  fma2(t1, x0p, w0.y);
            ulonglong2 w1v = *(const ulonglong2*)(sW + 256 + uu * 4);
            fma2(t0, x1p, w1v.x); fma2(t1, x1p, w1v.y);
            ulonglong2 w2v = *(const ulonglong2*)(sW + 512 + uu * 4);
            fma2(t0, x2p, w2v.x); fma2(t1, x2p, w2v.y);
            aif[u] = t0; ago[u] = t1;
        }

        // prefetch next timestep's x while the matmul runs
        if (t + 1 < TSTEPS) {
            const float* xn = xb + (t + 1) * FDIM;
            x0 = xn[0]; x1 = xn[1]; x2 = xn[2];
        }

        // z += h @ U   (k over 64 hidden units; broadcast LDS of U; FFMA2)
        #pragma unroll 4
        for (int k = 0; k < UNITS; k++) {
            const unsigned long long hk2 = pack2(shrow[k]);
            const float* uk = sU + (k << 8) + (ub << 2);
            #pragma unroll
            for (int u = 0; u < QUNITS; u++) {
                ulonglong2 uv = *(const ulonglong2*)(uk + (u << 2));
                fma2(aif[u], hk2, uv.x);
                fma2(ago[u], hk2, uv.y);
            }
        }

        __syncthreads();   // everyone finished reading old h

        #pragma unroll
        for (int u = 0; u < QUNITS; u++) {
            float2 zif = unpack2(aif[u]);
            float2 zgo = unpack2(ago[u]);
            float ig = sigf_(zif.x);
            float fg = sigf_(zif.y);
            float gg = tanhf_(zgo.x);
            float og = sigf_(zgo.y);
            float cn = fg * c[u] + ig * gg;
            float hn = og * tanhf_(cn);
            if (m) { c[u] = cn; shrow[ub + u] = hn; }
        }

        __syncthreads();   // new h visible for next step
    }

    // ---------------- head: relu(h@W1+b1) @ W2 + b2, softmax ----------------
    float* sW1 = sm + OFF_W1;
    float* sB1 = sm + OFF_B1;
    float* sW2 = sm + OFF_W2;
    float* sB2 = sm + OFF_B2;
    float* sH1 = sm + OFF_H1;

    for (int idx = tid; idx < 64 * 64; idx += NTHREADS) sW1[idx] = W1[idx];
    for (int idx = tid; idx < 64;      idx += NTHREADS) sB1[idx] = b1[idx];
    for (int idx = tid; idx < 320;     idx += NTHREADS) sW2[idx] = W2[idx];
    if (tid < 5) sB2[tid] = b2[tid];
    __syncthreads();

    #pragma unroll 4
    for (int j0 = 0; j0 < QUNITS; j0++) {
        const int j = ub + j0;
        float a = sB1[j];
        #pragma unroll 8
        for (int k = 0; k < 64; k++) a += shrow[k] * sW1[k * 64 + j];
        sH1[bl * 65 + j] = fmaxf(a, 0.0f);
    }
    __syncthreads();

    if (q == 0 && valid_b) {
        float lg[5];
        #pragma unroll
        for (int o = 0; o < 5; o++) lg[o] = sB2[o];
        #pragma unroll 8
        for (int j = 0; j < 64; j++) {
            const float hv = sH1[bl * 65 + j];
            #pragma unroll
            for (int o = 0; o < 5; o++) lg[o] += hv * sW2[j * 5 + o];
        }
        float mx = lg[0];
        #pragma unroll
        for (int o = 1; o < 5; o++) mx = fmaxf(mx, lg[o]);
        float e[5], s = 0.0f;
        #pragma unroll
        for (int o = 0; o < 5; o++) {
            e[o] = ex2f_(1.4426950408889634f * (lg[o] - mx));
            s += e[o];
        }
        const float inv = rcpf_(s);
        #pragma unroll
        for (int o = 0; o < 5; o++) out[(size_t)bglob * 5 + o] = e[o] * inv;
    }
}

extern "C" void kernel_launch(void* const* d_in, const int* in_sizes, int n_in,
                              void* d_out, int out_size) {
    const float* x  = (const float*)d_in[0];
    const float* W  = (const float*)d_in[1];
    const float* U  = (const float*)d_in[2];
    const float* b  = (const float*)d_in[3];
    const float* W1 = (const float*)d_in[4];
    const float* b1 = (const float*)d_in[5];
    const float* W2 = (const float*)d_in[6];
    const float* b2 = (const float*)d_in[7];
    float* out = (float*)d_out;

    const int B = in_sizes[0] / (TSTEPS * FDIM);
    const int grid = (B + TILE_B - 1) / TILE_B;

    cudaFuncSetAttribute(lstm_kernel,
                         cudaFuncAttributeMaxDynamicSharedMemorySize, SMEM_BYTES);
    lstm_kernel<<<grid, NTHREADS, SMEM_BYTES>>>(x, W, U, b, W1, b1, W2, b2, out, B);
}

// round 2
// speedup vs baseline: 1.5225x; 1.5225x over previous
#include <cuda_runtime.h>

#define TSTEPS  100
#define FDIM    3
#define TILE_B  128
#define NTHREADS 256

#define P_H 68      // padded row-dim of transposed h tile (16B-aligned, bank-skewed)
#define KS  288     // floats per k-row of sU/sW (8 uo-blocks * 36)
#define UOS 36      // uo-block stride in floats (bank skew: 36 % 32 = 4)

#define OFF_U 0                       // 64*288 = 18432 floats
#define OFF_W 18432                   // 3*288 = 864
#define OFF_B (18432 + 864)           // 288
#define OFF_H (OFF_B + 288)           // 2 groups * 64*P_H = 8704
#define SMEM_FLOATS (OFF_H + 2*64*P_H)
#define SMEM_BYTES  (SMEM_FLOATS * 4)

// head phase reuses the (dead) sU region
#define HW1 0        // 64*64 = 4096
#define HB1 4096     // 64
#define HW2 4160     // 320
#define HB2 4480     // 8
#define HH1 8192     // 2 * 64*P_H = 8704  (ends 16896 < OFF_W region start? stays inside old sU+sW)

// ---------------- f32x2 packed-math helpers ----------------
__device__ __forceinline__ unsigned long long pack2(float x) {
    unsigned long long r;
    asm("mov.b64 %0, {%1, %1};" : "=l"(r) : "f"(x));
    return r;
}
__device__ __forceinline__ void fma2(unsigned long long& d,
                                     unsigned long long a,
                                     unsigned long long b) {
    asm("fma.rn.f32x2 %0, %1, %2, %0;" : "+l"(d) : "l"(a), "l"(b));
}
__device__ __forceinline__ float2 unpack2(unsigned long long v) {
    float2 f;
    asm("mov.b64 {%0, %1}, %2;" : "=f"(f.x), "=f"(f.y) : "l"(v));
    return f;
}
__device__ __forceinline__ float ex2f_(float x) {
    float y; asm("ex2.approx.f32 %0, %1;" : "=f"(y) : "f"(x)); return y;
}
__device__ __forceinline__ float rcpf_(float x) {
    float y; asm("rcp.approx.f32 %0, %1;" : "=f"(y) : "f"(x)); return y;
}
__device__ __forceinline__ float sigf_(float x) {
    return rcpf_(1.0f + ex2f_(-1.4426950408889634f * x));
}
__device__ __forceinline__ float tanhf_(float x) {
    return 1.0f - 2.0f * rcpf_(1.0f + ex2f_(2.8853900817779268f * x));
}
__device__ __forceinline__ void barg(int id) {
    asm volatile("bar.sync %0, 128;" :: "r"(id) : "memory");
}

__global__ void __launch_bounds__(NTHREADS, 1)
lstm_kernel(const float* __restrict__ x,  const float* __restrict__ W,
            const float* __restrict__ U,  const float* __restrict__ b,
            const float* __restrict__ W1, const float* __restrict__ b1,
            const float* __restrict__ W2, const float* __restrict__ b2,
            float* __restrict__ out, int B)
{
    extern __shared__ float sm[];
    const int tid = threadIdx.x;
    const int g   = tid >> 7;        // group 0/1 (64 rows each)
    const int lt  = tid & 127;
    const int uo  = lt >> 4;         // unit-octet 0..7  (8 units each)
    const int rq  = lt & 15;         // row-quad 0..15   (4 rows each)
    const int barid = 1 + g;

    // ---- stage U/W/b with skewed layout sU[k*KS + uo*UOS + i*4 + gate] ----
    for (int idx = tid; idx < 64 * 256; idx += NTHREADS) {
        int k = idx >> 8, rem = idx & 255, gate = rem >> 6, u = rem & 63;
        sm[OFF_U + k * KS + (u >> 3) * UOS + (u & 7) * 4 + gate] = U[idx];
    }
    for (int idx = tid; idx < 3 * 256; idx += NTHREADS) {
        int f = idx >> 8, rem = idx & 255, gate = rem >> 6, u = rem & 63;
        sm[OFF_W + f * KS + (u >> 3) * UOS + (u & 7) * 4 + gate] = W[idx];
    }
    for (int idx = tid; idx < 256; idx += NTHREADS) {
        int gate = idx >> 6, u = idx & 63;
        sm[OFF_B + (u >> 3) * UOS + (u & 7) * 4 + gate] = b[idx];
    }
    for (int idx = tid; idx < 2 * 64 * P_H; idx += NTHREADS) sm[OFF_H + idx] = 0.0f;

    float* sHg = sm + OFF_H + g * (64 * P_H);   // transposed h: [unit][row]

    float c[32];
    #pragma unroll
    for (int z = 0; z < 32; z++) c[z] = 0.0f;

    const int rowbase = blockIdx.x * TILE_B + g * 64 + rq * 4;
    const float* xp[4];
    #pragma unroll
    for (int j = 0; j < 4; j++) {
        int r = rowbase + j; if (r >= B) r = B - 1;
        xp[j] = x + (size_t)r * (TSTEPS * FDIM);
    }
    float xc[12];
    #pragma unroll
    for (int j = 0; j < 4; j++)
        #pragma unroll
        for (int f = 0; f < 3; f++) xc[j * 3 + f] = xp[j][f];

    __syncthreads();

    unsigned long long aif[32], ago[32];

    for (int t = 0; t < TSTEPS; t++) {
        // prefetch next timestep's x (overlaps with the matmul below)
        float xn[12];
        if (t + 1 < TSTEPS) {
            #pragma unroll
            for (int j = 0; j < 4; j++) {
                const float* xq = xp[j] + (t + 1) * 3;
                xn[j * 3 + 0] = xq[0]; xn[j * 3 + 1] = xq[1]; xn[j * 3 + 2] = xq[2];
            }
        }

        bool m[4];
        unsigned long long xpk[12];
        #pragma unroll
        for (int j = 0; j < 4; j++) {
            m[j] = (xc[j*3] != 0.0f) || (xc[j*3+1] != 0.0f) || (xc[j*3+2] != 0.0f);
            xpk[j*3+0] = pack2(xc[j*3+0]);
            xpk[j*3+1] = pack2(xc[j*3+1]);
            xpk[j*3+2] = pack2(xc[j*3+2]);
        }

        // acc = bias + x @ W
        #pragma unroll
        for (int i = 0; i < 8; i++) {
            ulonglong2 bb = *(const ulonglong2*)(sm + OFF_B + uo*UOS + i*4);
            ulonglong2 w0 = *(const ulonglong2*)(sm + OFF_W + 0*KS + uo*UOS + i*4);
            ulonglong2 w1 = *(const ulonglong2*)(sm + OFF_W + 1*KS + uo*UOS + i*4);
            ulonglong2 w2 = *(const ulonglong2*)(sm + OFF_W + 2*KS + uo*UOS + i*4);
            #pragma unroll
            for (int j = 0; j < 4; j++) {
                unsigned long long a0 = bb.x, a1 = bb.y;
                fma2(a0, xpk[j*3+0], w0.x); fma2(a1, xpk[j*3+0], w0.y);
                fma2(a0, xpk[j*3+1], w1.x); fma2(a1, xpk[j*3+1], w1.y);
                fma2(a0, xpk[j*3+2], w2.x); fma2(a1, xpk[j*3+2], w2.y);
                aif[j*8+i] = a0; ago[j*8+i] = a1;
            }
        }

        // z += h @ U : per k, 1 LDS.128 (h, 4 rows) + 8 LDS.128 (U) + 64 FFMA2
        #pragma unroll 4
        for (int k = 0; k < 64; k++) {
            float4 hv = *(const float4*)(sHg + k * P_H + rq * 4);
            unsigned long long h0 = pack2(hv.x), h1 = pack2(hv.y);
            unsigned long long h2 = pack2(hv.z), h3 = pack2(hv.w);
            const float* uk = sm + OFF_U + k * KS + uo * UOS;
            #pragma unroll
            for (int i = 0; i < 8; i++) {
                ulonglong2 uv = *(const ulonglong2*)(uk + i * 4);
                fma2(aif[0*8+i], h0, uv.x); fma2(ago[0*8+i], h0, uv.y);
                fma2(aif[1*8+i], h1, uv.x); fma2(ago[1*8+i], h1, uv.y);
                fma2(aif[2*8+i], h2, uv.x); fma2(ago[2*8+i], h2, uv.y);
                fma2(aif[3*8+i], h3, uv.x); fma2(ago[3*8+i], h3, uv.y);
            }
        }

        barg(barid);   // all reads of old h in this group done

        // gates + masked h/c update, h written transposed
        #pragma unroll
        for (int i = 0; i < 8; i++) {
            const int u = uo * 8 + i;
            float4 hold = *(const float4*)(sHg + u * P_H + rq * 4);
            float hq[4] = {hold.x, hold.y, hold.z, hold.w};
            float hw[4];
            #pragma unroll
            for (int j = 0; j < 4; j++) {
                float2 zif = unpack2(aif[j*8+i]);
                float2 zgo = unpack2(ago[j*8+i]);
                float ig = sigf_(zif.x);
                float fg = sigf_(zif.y);
                float gg = tanhf_(zgo.x);
                float og = sigf_(zgo.y);
                float cn = fg * c[j*8+i] + ig * gg;
                float hn = og * tanhf_(cn);
                c[j*8+i] = m[j] ? cn : c[j*8+i];
                hw[j]    = m[j] ? hn : hq[j];
            }
            float4 st; st.x = hw[0]; st.y = hw[1]; st.z = hw[2]; st.w = hw[3];
            *(float4*)(sHg + u * P_H + rq * 4) = st;
        }

        barg(barid);   // new h visible to the group

        if (t + 1 < TSTEPS) {
            #pragma unroll
            for (int z = 0; z < 12; z++) xc[z] = xn[z];
        }
    }

    // ---------------- head: relu(h@W1+b1) @ W2 + b2, softmax ----------------
    __syncthreads();
    for (int idx = tid; idx < 4096; idx += NTHREADS) sm[HW1 + idx] = W1[idx];
    for (int idx = tid; idx < 64;   idx += NTHREADS) sm[HB1 + idx] = b1[idx];
    for (int idx = tid; idx < 320;  idx += NTHREADS) sm[HW2 + idx] = W2[idx];
    if (tid < 5) sm[HB2 + tid] = b2[tid];
    __syncthreads();

    float* sH1g = sm + HH1 + g * (64 * P_H);
    {
        float acc[32];
        #pragma unroll
        for (int i = 0; i < 8; i++) {
            float bv = sm[HB1 + uo * 8 + i];
            #pragma unroll
            for (int j = 0; j < 4; j++) acc[j*8+i] = bv;
        }
        for (int k = 0; k < 64; k++) {
            float4 hv = *(const float4*)(sHg + k * P_H + rq * 4);
            #pragma unroll
            for (int i = 0; i < 8; i++) {
                float w = sm[HW1 + k * 64 + uo * 8 + i];
                acc[0*8+i] += hv.x * w;
                acc[1*8+i] += hv.y * w;
                acc[2*8+i] += hv.z * w;
                acc[3*8+i] += hv.w * w;
            }
        }
        #pragma unroll
        for (int i = 0; i < 8; i++) {
            float4 st;
            st.x = fmaxf(acc[0*8+i], 0.0f);
            st.y = fmaxf(acc[1*8+i], 0.0f);
            st.z = fmaxf(acc[2*8+i], 0.0f);
            st.w = fmaxf(acc[3*8+i], 0.0f);
            *(float4*)(sH1g + (uo * 8 + i) * P_H + rq * 4) = st;
        }
    }
    barg(barid);

    if (uo < 4) {
        const int rl = rq * 4 + uo;
        const int grow = blockIdx.x * TILE_B + g * 64 + rl;
        if (grow < B) {
            float lg[5];
            #pragma unroll
            for (int o = 0; o < 5; o++) lg[o] = sm[HB2 + o];
            for (int k = 0; k < 64; k++) {
                const float hv = sH1g[k * P_H + rl];
                #pragma unroll
                for (int o = 0; o < 5; o++) lg[o] += hv * sm[HW2 + k * 5 + o];
            }
            float mx = lg[0];
            #pragma unroll
            for (int o = 1; o < 5; o++) mx = fmaxf(mx, lg[o]);
            float e[5], s = 0.0f;
            #pragma unroll
            for (int o = 0; o < 5; o++) {
                e[o] = ex2f_(1.4426950408889634f * (lg[o] - mx));
                s += e[o];
            }
            const float inv = rcpf_(s);
            #pragma unroll
            for (int o = 0; o < 5; o++) out[(size_t)grow * 5 + o] = e[o] * inv;
        }
    }
}

extern "C" void kernel_launch(void* const* d_in, const int* in_sizes, int n_in,
                              void* d_out, int out_size) {
    const float* x  = (const float*)d_in[0];
    const float* W  = (const float*)d_in[1];
    const float* U  = (const float*)d_in[2];
    const float* b  = (const float*)d_in[3];
    const float* W1 = (const float*)d_in[4];
    const float* b1 = (const float*)d_in[5];
    const float* W2 = (const float*)d_in[6];
    const float* b2 = (const float*)d_in[7];
    float* out = (float*)d_out;

    const int B = in_sizes[0] / (TSTEPS * FDIM);
    const int grid = (B + TILE_B - 1) / TILE_B;

    cudaFuncSetAttribute(lstm_kernel,
                         cudaFuncAttributeMaxDynamicSharedMemorySize, SMEM_BYTES);
    lstm_kernel<<<grid, NTHREADS, SMEM_BYTES>>>(x, W, U, b, W1, b1, W2, b2, out, B);
}